// round 13
// baseline (speedup 1.0000x reference)
#include <cuda_runtime.h>
#include <cuda_fp16.h>
#include <math.h>
#include <stdint.h>

// Problem dims
#define BB 256
#define DD 128
#define FF 8
#define TT 128
#define HH 128
#define KDIM (DD*FF)        // 1024
#define G4H (4*HH)          // 512

// Scratch (device globals; no allocation allowed)
__device__ float g_ex[BB*DD];
__device__ float g_a[BB*DD];
__device__ __align__(256) float g_y[BB*TT*G4H];               // y[b][t][g], 64 MB
__device__ __align__(256) __half g_xh[(size_t)BB*TT*KDIM];    // [b][t][k] fp16, 64 MB
__device__ __align__(256) __half g_wh[G4H*KDIM];              // [g][k] fp16

// ---------------- baseline-PTX helpers ----------------
__device__ __forceinline__ uint32_t smem_u32(const void* p) {
    uint32_t a;
    asm("{ .reg .u64 t; cvta.to.shared.u64 t, %1; cvt.u32.u64 %0, t; }" : "=r"(a) : "l"(p));
    return a;
}
#define SWZ64(o) ((o) ^ (((o) >> 3) & 0x30))

#define CP_ASYNC16(dst, src) \
    asm volatile("cp.async.cg.shared.global [%0], [%1], 16;" :: "r"(dst), "l"(src))
#define CP_COMMIT() asm volatile("cp.async.commit_group;" ::: "memory")
#define CP_WAIT(n)  asm volatile("cp.async.wait_group %0;" :: "n"(n) : "memory")

#define LDSM_X4(r0, r1, r2, r3, a) \
    asm volatile("ldmatrix.sync.aligned.m8n8.x4.shared.b16 {%0,%1,%2,%3}, [%4];" \
        : "=r"(r0), "=r"(r1), "=r"(r2), "=r"(r3) : "r"(a))

#define MMA16816F16(d, a0, a1, a2, a3, b0, b1) \
    asm volatile("mma.sync.aligned.m16n8k16.row.col.f32.f16.f16.f32 " \
        "{%0,%1,%2,%3},{%4,%5,%6,%7},{%8,%9},{%0,%1,%2,%3};" \
        : "+f"((d)[0]), "+f"((d)[1]), "+f"((d)[2]), "+f"((d)[3]) \
        : "r"(a0), "r"(a1), "r"(a2), "r"(a3), "r"(b0), "r"(b1))

#define FMA_F32X2(d, a, b) \
    asm("fma.rn.f32x2 %0, %1, %2, %0;" : "+l"(d) : "l"(a), "l"(b))
__device__ __forceinline__ float p2lo(unsigned long long v) {
    return __uint_as_float((unsigned)(v & 0xffffffffull));
}
__device__ __forceinline__ float p2hi(unsigned long long v) {
    return __uint_as_float((unsigned)(v >> 32));
}

// ---------------------------------------------------------------------------
// K1: ex[b,d] = sum_{f,t} input[b,d,f,t] * w_x[f*T+t]; one warp per (b,d)
// ---------------------------------------------------------------------------
__global__ void k1_ex(const float* __restrict__ input, const float* __restrict__ w_attn) {
    const float* w_x = w_attn + 2*HH;
    int warp = (blockIdx.x * blockDim.x + threadIdx.x) >> 5;
    int lane = threadIdx.x & 31;
    if (warp >= BB*DD) return;
    const float4* base = (const float4*)(input + (size_t)warp * KDIM);
    const float4* w4 = (const float4*)w_x;
    float s = 0.f;
    #pragma unroll
    for (int i = 0; i < 8; i++) {
        float4 v = base[lane + 32*i];
        float4 w = __ldg(&w4[lane + 32*i]);
        s += v.x*w.x + v.y*w.y + v.z*w.z + v.w*w.w;
    }
    #pragma unroll
    for (int o = 16; o > 0; o >>= 1) s += __shfl_down_sync(0xffffffffu, s, o);
    if (lane == 0) g_ex[warp] = s;
}

// ---------------------------------------------------------------------------
// K1b: a[b,:] = softmax(ex[b,:]) over D=128
// ---------------------------------------------------------------------------
__global__ void k1b_softmax() {
    __shared__ float red[4];
    int b = blockIdx.x;
    int d = threadIdx.x;
    int lane = d & 31, w = d >> 5;
    float v = g_ex[b*DD + d];
    float m = v;
    #pragma unroll
    for (int o = 16; o > 0; o >>= 1) m = fmaxf(m, __shfl_xor_sync(0xffffffffu, m, o));
    if (lane == 0) red[w] = m;
    __syncthreads();
    m = fmaxf(fmaxf(red[0], red[1]), fmaxf(red[2], red[3]));
    float e = expf(v - m);
    float s = e;
    #pragma unroll
    for (int o = 16; o > 0; o >>= 1) s += __shfl_xor_sync(0xffffffffu, s, o);
    __syncthreads();
    if (lane == 0) red[w] = s;
    __syncthreads();
    s = red[0] + red[1] + red[2] + red[3];
    g_a[b*DD + d] = e / s;
}

// ---------------------------------------------------------------------------
// kW: round W_ih to fp16, [g][k] K-major
// ---------------------------------------------------------------------------
__global__ void k_wsplit(const float* __restrict__ W_ih) {
    int idx = blockIdx.x * 256 + threadIdx.x;
    if (idx >= G4H*KDIM/2) return;
    float2 v = ((const float2*)W_ih)[idx];
    __half h0 = __float2half_rn(v.x), h1 = __float2half_rn(v.y);
    ((uint32_t*)g_wh)[idx] = (uint32_t)__half_as_ushort(h0) | ((uint32_t)__half_as_ushort(h1) << 16);
}

// ---------------------------------------------------------------------------
// k_prep: xhat = a[b,k>>3] * input[b,k,t]; fp16 round; transpose to [b][t][k]
// (clock canary: identical since round 10 — compare dur across runs)
// ---------------------------------------------------------------------------
__global__ __launch_bounds__(256) void k_prep(const float* __restrict__ input) {
    __shared__ float tile[64][129];
    int b = blockIdx.y, k0 = blockIdx.x * 64;
    int tid = threadIdx.x;
    int lane = tid & 31, r = tid >> 5;
    #pragma unroll
    for (int it = 0; it < 8; it++) {
        int row = it*8 + r;
        const float4 v = *(const float4*)(input + ((size_t)b*KDIM + k0 + row)*TT + lane*4);
        float s = g_a[b*DD + ((k0 + row) >> 3)];
        tile[row][lane*4+0] = v.x*s;
        tile[row][lane*4+1] = v.y*s;
        tile[row][lane*4+2] = v.z*s;
        tile[row][lane*4+3] = v.w*s;
    }
    __syncthreads();
    int kk = lane * 2;
    #pragma unroll
    for (int it = 0; it < 16; it++) {
        int t = it*8 + r;
        __half h0 = __float2half_rn(tile[kk][t]);
        __half h1 = __float2half_rn(tile[kk+1][t]);
        uint32_t hp = (uint32_t)__half_as_ushort(h0) | ((uint32_t)__half_as_ushort(h1) << 16);
        size_t base = (size_t)(b*TT + t)*(KDIM/2) + (k0 >> 1);
        ((uint32_t*)g_xh)[base + lane] = hp;
    }
}

// ---------------------------------------------------------------------------
// k2_mma: single-pass fp16 (xh * wh), chunk_k=32 (SW64),
// 2-stage cp.async double buffer, 2 CTAs/SM. (unchanged)
// ---------------------------------------------------------------------------
#define S_A 0
#define S_B 8192
#define K2_STAGE 16384
#define K2_SMEM (2*K2_STAGE)

__device__ __forceinline__ void k2_load_chunk(uint32_t dstbase, int b, int gbase,
                                              int k0, int tid) {
    const char* pxh = (const char*)g_xh;
    const char* pwh = (const char*)g_wh;
    #pragma unroll
    for (int q = 0; q < 2; q++) {
        int u = tid + 256*q;          // 0..511
        int row = u >> 2, l4 = u & 3;
        uint32_t sw = SWZ64((uint32_t)(row*64 + l4*16));
        size_t aoff = ((size_t)(b*TT + row)*KDIM + k0)*2 + l4*16;
        size_t boff = ((size_t)(gbase + row)*KDIM + k0)*2 + l4*16;
        CP_ASYNC16(dstbase + S_A + sw, pxh + aoff);
        CP_ASYNC16(dstbase + S_B + sw, pwh + boff);
    }
}

__global__ __launch_bounds__(256, 2) void k2_mma() {
    extern __shared__ char smem[];
    uint32_t sb = smem_u32(smem);
    int tid = threadIdx.x;
    int lane = tid & 31, wid = tid >> 5;
    int b = blockIdx.y, gbase = blockIdx.x * 128;
    int wt = wid & 3;        // t block: wt*32
    int wg = wid >> 2;       // g block: wg*64

    float acc[2][8][4];
    #pragma unroll
    for (int mi = 0; mi < 2; mi++)
        #pragma unroll
        for (int ni = 0; ni < 8; ni++)
            #pragma unroll
            for (int q = 0; q < 4; q++) acc[mi][ni][q] = 0.f;

    int a_row_base = wt*32 + (lane & 15);
    int a_col = (lane >> 4) * 16;
    int b_row_base = wg*64 + ((lane >> 4) * 8) + (lane & 7);
    int b_col = ((lane >> 3) & 1) * 16;

    k2_load_chunk(sb, b, gbase, 0, tid);
    CP_COMMIT();

    int buf = 0;
    for (int chunk = 0; chunk < 32; chunk++) {
        if (chunk < 31) {
            k2_load_chunk(sb + (buf ^ 1)*K2_STAGE, b, gbase, (chunk+1)*32, tid);
            CP_COMMIT();
            CP_WAIT(1);
        } else {
            CP_WAIT(0);
        }
        __syncthreads();

        uint32_t base = sb + buf*K2_STAGE;
        #pragma unroll
        for (int ks = 0; ks < 2; ks++) {
            uint32_t ah[2][4];
            #pragma unroll
            for (int mi = 0; mi < 2; mi++) {
                uint32_t off = SWZ64((uint32_t)((a_row_base + mi*16)*64 + ks*32 + a_col));
                LDSM_X4(ah[mi][0], ah[mi][1], ah[mi][2], ah[mi][3], base + S_A + off);
            }
            #pragma unroll
            for (int p = 0; p < 4; p++) {
                uint32_t off = SWZ64((uint32_t)((b_row_base + p*16)*64 + ks*32 + b_col));
                uint32_t bh[4];
                LDSM_X4(bh[0], bh[1], bh[2], bh[3], base + S_B + off);
                #pragma unroll
                for (int mi = 0; mi < 2; mi++)
                    #pragma unroll
                    for (int j = 0; j < 2; j++)
                        MMA16816F16(acc[mi][p*2+j], ah[mi][0], ah[mi][1], ah[mi][2], ah[mi][3],
                                    bh[j*2], bh[j*2+1]);
            }
        }
        __syncthreads();
        buf ^= 1;
    }

    // Epilogue
    int r0 = wt*32 + (lane >> 2);
    int c0 = gbase + wg*64 + (lane & 3)*2;
    #pragma unroll
    for (int mi = 0; mi < 2; mi++) {
        #pragma unroll
        for (int ni = 0; ni < 8; ni++) {
            int row = r0 + mi*16;
            int col = c0 + ni*8;
            float* p0 = g_y + (size_t)(b*TT + row)*G4H + col;
            float* p1 = g_y + (size_t)(b*TT + row + 8)*G4H + col;
            *(float2*)p0 = make_float2(acc[mi][ni][0], acc[mi][ni][1]);
            *(float2*)p1 = make_float2(acc[mi][ni][2], acc[mi][ni][3]);
        }
    }
}

// ---------------------------------------------------------------------------
// K3: persistent recurrence — FULL W_hh row in registers (64 regs/thread).
// smem only for hs/cs/gs/bias (8 KB). Two barriers per step (proven safe).
// ---------------------------------------------------------------------------
__device__ __forceinline__ float sigm(float x) { return 1.f / (1.f + expf(-x)); }

__global__ __launch_bounds__(512, 1) void k3_lstm(const float* __restrict__ W_hh,
                                                  const float* __restrict__ b_ih,
                                                  const float* __restrict__ b_hh,
                                                  float* __restrict__ out) {
    __shared__ float hs[2*HH];
    __shared__ float cs[2*HH];
    __shared__ float gs[2*G4H];
    __shared__ float bias[G4H];

    int tid = threadIdx.x;
    int b0 = blockIdx.x * 2;
    const int g = tid;

    bias[tid] = b_ih[tid] + b_hh[tid];
    if (tid < 2*HH) { hs[tid] = 0.f; cs[tid] = 0.f; }

    // FULL W row in registers: k in [0,128) = 32 ulonglong2 = 64 regs
    ulonglong2 wr2[32];
    #pragma unroll
    for (int i = 0; i < 32; i++)
        wr2[i] = *(const ulonglong2*)(W_hh + (size_t)g*HH + 4*i);

    __syncthreads();

    const float myBias = bias[g];
    const float* h0 = hs;
    const float* h1 = hs + HH;
    const float* y0p = g_y + ((size_t)b0*TT)*G4H + g;
    const float* y1p = g_y + ((size_t)(b0+1)*TT)*G4H + g;

    float yn0 = *y0p, yn1 = *y1p;

    for (int t = 0; t < TT; t++) {
        float base0 = yn0 + myBias;
        float base1 = yn1 + myBias;
        if (t + 1 < TT) {
            yn0 = y0p[(size_t)(t+1)*G4H];
            yn1 = y1p[(size_t)(t+1)*G4H];
        }
        unsigned long long a0p = 0ull, a0q = 0ull, a1p = 0ull, a1q = 0ull;
        #pragma unroll
        for (int i = 0; i < 32; i++) {
            ulonglong2 w = wr2[i];
            ulonglong2 a = *(const ulonglong2*)(h0 + 4*i);
            ulonglong2 bv = *(const ulonglong2*)(h1 + 4*i);
            FMA_F32X2(a0p, w.x, a.x);
            FMA_F32X2(a0q, w.y, a.y);
            FMA_F32X2(a1p, w.x, bv.x);
            FMA_F32X2(a1q, w.y, bv.y);
        }
        gs[g]       = base0 + p2lo(a0p) + p2hi(a0p) + p2lo(a0q) + p2hi(a0q);
        gs[G4H + g] = base1 + p2lo(a1p) + p2hi(a1p) + p2lo(a1q) + p2hi(a1q);
        __syncthreads();
        if (tid < 2*HH) {
            int bb = tid >> 7;
            int j  = tid & (HH-1);
            const float* G = gs + bb*G4H;
            float iv = G[j], fv = G[HH + j], gv = G[2*HH + j], ov = G[3*HH + j];
            float c  = cs[bb*HH + j];
            float cn = sigm(fv)*c + sigm(iv)*tanhf(gv);
            float hn = sigm(ov)*tanhf(cn);
            cs[bb*HH + j] = cn;
            hs[bb*HH + j] = hn;
            out[((size_t)(b0+bb)*TT + t)*HH + j] = hn;
        }
        __syncthreads();
    }
}

// ---------------------------------------------------------------------------
extern "C" void kernel_launch(void* const* d_in, const int* in_sizes, int n_in,
                              void* d_out, int out_size) {
    const float* input  = (const float*)d_in[0];  // (B,D,F,T)
    const float* w_attn = (const float*)d_in[1];  // (F*T + 2H,)
    // d_in[2] = b_attn (unused: softmax is shift-invariant)
    const float* W_ih   = (const float*)d_in[3];  // (4H, D*F)
    const float* W_hh   = (const float*)d_in[4];  // (4H, H)
    const float* b_ih   = (const float*)d_in[5];  // (4H,)
    const float* b_hh   = (const float*)d_in[6];  // (4H,)
    float* out = (float*)d_out;                   // (B, T, H)

    k1_ex<<<4096, 256>>>(input, w_attn);
    k1b_softmax<<<BB, DD>>>();
    k_wsplit<<<(G4H*KDIM/2 + 255)/256, 256>>>(W_ih);
    {
        dim3 grid(KDIM/64, BB);
        k_prep<<<grid, 256>>>(input);
    }
    {
        cudaFuncSetAttribute(k2_mma, cudaFuncAttributeMaxDynamicSharedMemorySize, K2_SMEM);
        dim3 grid(G4H/128, BB);
        k2_mma<<<grid, 256, K2_SMEM>>>();
    }
    k3_lstm<<<BB/2, 512>>>(W_hh, b_ih, b_hh, out);
}

// round 16
// speedup vs baseline: 2.0251x; 2.0251x over previous
#include <cuda_runtime.h>
#include <cuda_fp16.h>
#include <math.h>
#include <stdint.h>

// Problem dims
#define BB 256
#define DD 128
#define FF 8
#define TT 128
#define HH 128
#define KDIM (DD*FF)        // 1024
#define G4H (4*HH)          // 512

// Scratch (device globals; no allocation allowed)
__device__ float g_ex[BB*DD];
__device__ float g_a[BB*DD];
__device__ __align__(256) float g_y[BB*TT*G4H];               // y[b][t][g], 64 MB
__device__ __align__(256) __half g_xh[(size_t)BB*TT*KDIM];    // [b][t][k] fp16, 64 MB
__device__ __align__(256) __half g_wh[G4H*KDIM];              // [g][k] fp16

// ---------------- baseline-PTX helpers ----------------
__device__ __forceinline__ uint32_t smem_u32(const void* p) {
    uint32_t a;
    asm("{ .reg .u64 t; cvta.to.shared.u64 t, %1; cvt.u32.u64 %0, t; }" : "=r"(a) : "l"(p));
    return a;
}
#define SWZ64(o) ((o) ^ (((o) >> 3) & 0x30))

#define CP_ASYNC16(dst, src) \
    asm volatile("cp.async.cg.shared.global [%0], [%1], 16;" :: "r"(dst), "l"(src))
#define CP_COMMIT() asm volatile("cp.async.commit_group;" ::: "memory")
#define CP_WAIT(n)  asm volatile("cp.async.wait_group %0;" :: "n"(n) : "memory")

#define LDSM_X4(r0, r1, r2, r3, a) \
    asm volatile("ldmatrix.sync.aligned.m8n8.x4.shared.b16 {%0,%1,%2,%3}, [%4];" \
        : "=r"(r0), "=r"(r1), "=r"(r2), "=r"(r3) : "r"(a))

#define MMA16816F16(d, a0, a1, a2, a3, b0, b1) \
    asm volatile("mma.sync.aligned.m16n8k16.row.col.f32.f16.f16.f32 " \
        "{%0,%1,%2,%3},{%4,%5,%6,%7},{%8,%9},{%0,%1,%2,%3};" \
        : "+f"((d)[0]), "+f"((d)[1]), "+f"((d)[2]), "+f"((d)[3]) \
        : "r"(a0), "r"(a1), "r"(a2), "r"(a3), "r"(b0), "r"(b1))

#define FMA_F32X2(d, a, b) \
    asm("fma.rn.f32x2 %0, %1, %2, %0;" : "+l"(d) : "l"(a), "l"(b))
__device__ __forceinline__ float p2lo(unsigned long long v) {
    return __uint_as_float((unsigned)(v & 0xffffffffull));
}
__device__ __forceinline__ float p2hi(unsigned long long v) {
    return __uint_as_float((unsigned)(v >> 32));
}

// ---------------------------------------------------------------------------
// K1: ex[b,d] = sum_{f,t} input[b,d,f,t] * w_x[f*T+t]; one warp per (b,d)
// ---------------------------------------------------------------------------
__global__ void k1_ex(const float* __restrict__ input, const float* __restrict__ w_attn) {
    const float* w_x = w_attn + 2*HH;
    int warp = (blockIdx.x * blockDim.x + threadIdx.x) >> 5;
    int lane = threadIdx.x & 31;
    if (warp >= BB*DD) return;
    const float4* base = (const float4*)(input + (size_t)warp * KDIM);
    const float4* w4 = (const float4*)w_x;
    float s = 0.f;
    #pragma unroll
    for (int i = 0; i < 8; i++) {
        float4 v = base[lane + 32*i];
        float4 w = __ldg(&w4[lane + 32*i]);
        s += v.x*w.x + v.y*w.y + v.z*w.z + v.w*w.w;
    }
    #pragma unroll
    for (int o = 16; o > 0; o >>= 1) s += __shfl_down_sync(0xffffffffu, s, o);
    if (lane == 0) g_ex[warp] = s;
}

// ---------------------------------------------------------------------------
// K1b: a[b,:] = softmax(ex[b,:]) over D=128
// ---------------------------------------------------------------------------
__global__ void k1b_softmax() {
    __shared__ float red[4];
    int b = blockIdx.x;
    int d = threadIdx.x;
    int lane = d & 31, w = d >> 5;
    float v = g_ex[b*DD + d];
    float m = v;
    #pragma unroll
    for (int o = 16; o > 0; o >>= 1) m = fmaxf(m, __shfl_xor_sync(0xffffffffu, m, o));
    if (lane == 0) red[w] = m;
    __syncthreads();
    m = fmaxf(fmaxf(red[0], red[1]), fmaxf(red[2], red[3]));
    float e = expf(v - m);
    float s = e;
    #pragma unroll
    for (int o = 16; o > 0; o >>= 1) s += __shfl_xor_sync(0xffffffffu, s, o);
    __syncthreads();
    if (lane == 0) red[w] = s;
    __syncthreads();
    s = red[0] + red[1] + red[2] + red[3];
    g_a[b*DD + d] = e / s;
}

// ---------------------------------------------------------------------------
// kW: round W_ih to fp16, [g][k] K-major
// ---------------------------------------------------------------------------
__global__ void k_wsplit(const float* __restrict__ W_ih) {
    int idx = blockIdx.x * 256 + threadIdx.x;
    if (idx >= G4H*KDIM/2) return;
    float2 v = ((const float2*)W_ih)[idx];
    __half h0 = __float2half_rn(v.x), h1 = __float2half_rn(v.y);
    ((uint32_t*)g_wh)[idx] = (uint32_t)__half_as_ushort(h0) | ((uint32_t)__half_as_ushort(h1) << 16);
}

// ---------------------------------------------------------------------------
// k_prep: xhat = a[b,k>>3] * input[b,k,t]; fp16 round; transpose to [b][t][k]
// (clock canary: identical since round 10 — compare dur across runs)
// ---------------------------------------------------------------------------
__global__ __launch_bounds__(256) void k_prep(const float* __restrict__ input) {
    __shared__ float tile[64][129];
    int b = blockIdx.y, k0 = blockIdx.x * 64;
    int tid = threadIdx.x;
    int lane = tid & 31, r = tid >> 5;
    #pragma unroll
    for (int it = 0; it < 8; it++) {
        int row = it*8 + r;
        const float4 v = *(const float4*)(input + ((size_t)b*KDIM + k0 + row)*TT + lane*4);
        float s = g_a[b*DD + ((k0 + row) >> 3)];
        tile[row][lane*4+0] = v.x*s;
        tile[row][lane*4+1] = v.y*s;
        tile[row][lane*4+2] = v.z*s;
        tile[row][lane*4+3] = v.w*s;
    }
    __syncthreads();
    int kk = lane * 2;
    #pragma unroll
    for (int it = 0; it < 16; it++) {
        int t = it*8 + r;
        __half h0 = __float2half_rn(tile[kk][t]);
        __half h1 = __float2half_rn(tile[kk+1][t]);
        uint32_t hp = (uint32_t)__half_as_ushort(h0) | ((uint32_t)__half_as_ushort(h1) << 16);
        size_t base = (size_t)(b*TT + t)*(KDIM/2) + (k0 >> 1);
        ((uint32_t*)g_xh)[base + lane] = hp;
    }
}

// ---------------------------------------------------------------------------
// k2_mma: single-pass fp16 (xh * wh), chunk_k=32 (SW64),
// 2-stage cp.async double buffer, 2 CTAs/SM. (unchanged, proven)
// ---------------------------------------------------------------------------
#define S_A 0
#define S_B 8192
#define K2_STAGE 16384
#define K2_SMEM (2*K2_STAGE)

__device__ __forceinline__ void k2_load_chunk(uint32_t dstbase, int b, int gbase,
                                              int k0, int tid) {
    const char* pxh = (const char*)g_xh;
    const char* pwh = (const char*)g_wh;
    #pragma unroll
    for (int q = 0; q < 2; q++) {
        int u = tid + 256*q;          // 0..511
        int row = u >> 2, l4 = u & 3;
        uint32_t sw = SWZ64((uint32_t)(row*64 + l4*16));
        size_t aoff = ((size_t)(b*TT + row)*KDIM + k0)*2 + l4*16;
        size_t boff = ((size_t)(gbase + row)*KDIM + k0)*2 + l4*16;
        CP_ASYNC16(dstbase + S_A + sw, pxh + aoff);
        CP_ASYNC16(dstbase + S_B + sw, pwh + boff);
    }
}

__global__ __launch_bounds__(256, 2) void k2_mma() {
    extern __shared__ char smem[];
    uint32_t sb = smem_u32(smem);
    int tid = threadIdx.x;
    int lane = tid & 31, wid = tid >> 5;
    int b = blockIdx.y, gbase = blockIdx.x * 128;
    int wt = wid & 3;        // t block: wt*32
    int wg = wid >> 2;       // g block: wg*64

    float acc[2][8][4];
    #pragma unroll
    for (int mi = 0; mi < 2; mi++)
        #pragma unroll
        for (int ni = 0; ni < 8; ni++)
            #pragma unroll
            for (int q = 0; q < 4; q++) acc[mi][ni][q] = 0.f;

    int a_row_base = wt*32 + (lane & 15);
    int a_col = (lane >> 4) * 16;
    int b_row_base = wg*64 + ((lane >> 4) * 8) + (lane & 7);
    int b_col = ((lane >> 3) & 1) * 16;

    k2_load_chunk(sb, b, gbase, 0, tid);
    CP_COMMIT();

    int buf = 0;
    for (int chunk = 0; chunk < 32; chunk++) {
        if (chunk < 31) {
            k2_load_chunk(sb + (buf ^ 1)*K2_STAGE, b, gbase, (chunk+1)*32, tid);
            CP_COMMIT();
            CP_WAIT(1);
        } else {
            CP_WAIT(0);
        }
        __syncthreads();

        uint32_t base = sb + buf*K2_STAGE;
        #pragma unroll
        for (int ks = 0; ks < 2; ks++) {
            uint32_t ah[2][4];
            #pragma unroll
            for (int mi = 0; mi < 2; mi++) {
                uint32_t off = SWZ64((uint32_t)((a_row_base + mi*16)*64 + ks*32 + a_col));
                LDSM_X4(ah[mi][0], ah[mi][1], ah[mi][2], ah[mi][3], base + S_A + off);
            }
            #pragma unroll
            for (int p = 0; p < 4; p++) {
                uint32_t off = SWZ64((uint32_t)((b_row_base + p*16)*64 + ks*32 + b_col));
                uint32_t bh[4];
                LDSM_X4(bh[0], bh[1], bh[2], bh[3], base + S_B + off);
                #pragma unroll
                for (int mi = 0; mi < 2; mi++)
                    #pragma unroll
                    for (int j = 0; j < 2; j++)
                        MMA16816F16(acc[mi][p*2+j], ah[mi][0], ah[mi][1], ah[mi][2], ah[mi][3],
                                    bh[j*2], bh[j*2+1]);
            }
        }
        __syncthreads();
        buf ^= 1;
    }

    // Epilogue
    int r0 = wt*32 + (lane >> 2);
    int c0 = gbase + wg*64 + (lane & 3)*2;
    #pragma unroll
    for (int mi = 0; mi < 2; mi++) {
        #pragma unroll
        for (int ni = 0; ni < 8; ni++) {
            int row = r0 + mi*16;
            int col = c0 + ni*8;
            float* p0 = g_y + (size_t)(b*TT + row)*G4H + col;
            float* p1 = g_y + (size_t)(b*TT + row + 8)*G4H + col;
            *(float2*)p0 = make_float2(acc[mi][ni][0], acc[mi][ni][1]);
            *(float2*)p1 = make_float2(acc[mi][ni][2], acc[mi][ni][3]);
        }
    }
}

// ---------------------------------------------------------------------------
// K3: persistent recurrence. Hybrid W (WREG=64 regs + smem pitch-68, proven),
// gate-interleaved map (q=tid&3 gate, j=tid>>2 unit), gates gathered by
// shuffle, c in registers, DOUBLE-BUFFERED h -> ONE barrier per step.
// Wp stored in OWNER-TID order (conflict-free, same pattern as round 12).
// ---------------------------------------------------------------------------
#define WREG 64
#define WP_PITCH 68

__device__ __forceinline__ float sigm(float x) { return 1.f / (1.f + expf(-x)); }

__global__ __launch_bounds__(512, 1) void k3_lstm(const float* __restrict__ W_hh,
                                                  const float* __restrict__ b_ih,
                                                  const float* __restrict__ b_hh,
                                                  float* __restrict__ out) {
    extern __shared__ float sm[];
    float* Wp = sm;                        // 512 * WP_PITCH, owner-tid order
    float* hsb = Wp + G4H*WP_PITCH;        // [2 buffers][2 batches][128]

    int tid = threadIdx.x;
    int b0 = blockIdx.x * 2;
    int q = tid & 3;                       // gate: 0=i,1=f,2=g,3=o
    int j = tid >> 2;                      // hidden unit
    int g = q*HH + j;                      // my gate row

    // Fill Wp in owner-tid order: slot s holds W row g(s) = (s&3)*128 + (s>>2)
    for (int idx = tid; idx < G4H*(HH-WREG); idx += 512) {
        int s  = idx >> 6;                 // slot 0..511
        int kk = idx & 63;
        int gs_row = (s & 3)*HH + (s >> 2);
        Wp[s*WP_PITCH + kk] = W_hh[(size_t)gs_row*HH + WREG + kk];
    }
    if (tid < 4*HH) hsb[tid] = 0.f;        // zero both h buffers

    // register half of W row g: k in [0,64)
    ulonglong2 wr2[16];
    #pragma unroll
    for (int i = 0; i < 16; i++)
        wr2[i] = *(const ulonglong2*)(W_hh + (size_t)g*HH + 4*i);

    __syncthreads();

    const float myBias = b_ih[g] + b_hh[g];
    const float* wprow = Wp + tid*WP_PITCH;          // owner-tid order
    const float* y0p = g_y + ((size_t)b0*TT)*G4H + g;
    const float* y1p = g_y + ((size_t)(b0+1)*TT)*G4H + g;

    float c_reg = 0.f;                     // my cell state (valid for q<2)
    int lane = tid & 31;
    int lbase = lane & ~3;

    float yn0 = *y0p, yn1 = *y1p;

    for (int t = 0; t < TT; t++) {
        const float* hb = hsb + (t & 1) * (2*HH);        // read buffer
        float* hn_buf   = hsb + ((t+1) & 1) * (2*HH);    // write buffer
        const float* h0 = hb;
        const float* h1 = hb + HH;

        float base0 = yn0 + myBias;
        float base1 = yn1 + myBias;
        if (t + 1 < TT) {
            yn0 = y0p[(size_t)(t+1)*G4H];
            yn1 = y1p[(size_t)(t+1)*G4H];
        }
        unsigned long long a0p = 0ull, a0q = 0ull, a1p = 0ull, a1q = 0ull;
        // register-W section: k in [0,64); h reads are warp-broadcasts
        #pragma unroll
        for (int i = 0; i < 16; i++) {
            ulonglong2 w = wr2[i];
            ulonglong2 a = *(const ulonglong2*)(h0 + 4*i);
            ulonglong2 bv = *(const ulonglong2*)(h1 + 4*i);
            FMA_F32X2(a0p, w.x, a.x);
            FMA_F32X2(a0q, w.y, a.y);
            FMA_F32X2(a1p, w.x, bv.x);
            FMA_F32X2(a1q, w.y, bv.y);
        }
        // smem-W section: k in [64,128)
        #pragma unroll
        for (int i = 0; i < 16; i++) {
            ulonglong2 w = *(const ulonglong2*)(wprow + 4*i);
            ulonglong2 a = *(const ulonglong2*)(h0 + WREG + 4*i);
            ulonglong2 bv = *(const ulonglong2*)(h1 + WREG + 4*i);
            FMA_F32X2(a0p, w.x, a.x);
            FMA_F32X2(a0q, w.y, a.y);
            FMA_F32X2(a1p, w.x, bv.x);
            FMA_F32X2(a1q, w.y, bv.y);
        }
        float gate0 = base0 + p2lo(a0p) + p2hi(a0p) + p2lo(a0q) + p2hi(a0q);
        float gate1 = base1 + p2lo(a1p) + p2hi(a1p) + p2lo(a1q) + p2hi(a1q);

        // gather 4 gates of unit j (adjacent lanes); all lanes shuffle
        float i0 = __shfl_sync(0xffffffffu, gate0, lbase + 0);
        float f0 = __shfl_sync(0xffffffffu, gate0, lbase + 1);
        float g0 = __shfl_sync(0xffffffffu, gate0, lbase + 2);
        float o0 = __shfl_sync(0xffffffffu, gate0, lbase + 3);
        float i1 = __shfl_sync(0xffffffffu, gate1, lbase + 0);
        float f1 = __shfl_sync(0xffffffffu, gate1, lbase + 1);
        float g1 = __shfl_sync(0xffffffffu, gate1, lbase + 2);
        float o1 = __shfl_sync(0xffffffffu, gate1, lbase + 3);

        if (q < 2) {
            float iv = (q == 0) ? i0 : i1;
            float fv = (q == 0) ? f0 : f1;
            float gv = (q == 0) ? g0 : g1;
            float ov = (q == 0) ? o0 : o1;
            float cn = sigm(fv)*c_reg + sigm(iv)*tanhf(gv);
            float hn = sigm(ov)*tanhf(cn);
            c_reg = cn;
            hn_buf[q*HH + j] = hn;                       // other buffer: no race
            out[((size_t)(b0+q)*TT + t)*HH + j] = hn;
        }
        __syncthreads();                                  // ONE barrier per step
    }
}

// ---------------------------------------------------------------------------
extern "C" void kernel_launch(void* const* d_in, const int* in_sizes, int n_in,
                              void* d_out, int out_size) {
    const float* input  = (const float*)d_in[0];  // (B,D,F,T)
    const float* w_attn = (const float*)d_in[1];  // (F*T + 2H,)
    // d_in[2] = b_attn (unused: softmax is shift-invariant)
    const float* W_ih   = (const float*)d_in[3];  // (4H, D*F)
    const float* W_hh   = (const float*)d_in[4];  // (4H, H)
    const float* b_ih   = (const float*)d_in[5];  // (4H,)
    const float* b_hh   = (const float*)d_in[6];  // (4H,)
    float* out = (float*)d_out;                   // (B, T, H)

    k1_ex<<<4096, 256>>>(input, w_attn);
    k1b_softmax<<<BB, DD>>>();
    k_wsplit<<<(G4H*KDIM/2 + 255)/256, 256>>>(W_ih);
    {
        dim3 grid(KDIM/64, BB);
        k_prep<<<grid, 256>>>(input);
    }
    {
        cudaFuncSetAttribute(k2_mma, cudaFuncAttributeMaxDynamicSharedMemorySize, K2_SMEM);
        dim3 grid(G4H/128, BB);
        k2_mma<<<grid, 256, K2_SMEM>>>();
    }
    {
        int smem = (G4H*WP_PITCH + 4*HH) * (int)sizeof(float);
        cudaFuncSetAttribute(k3_lstm, cudaFuncAttributeMaxDynamicSharedMemorySize, smem);
        k3_lstm<<<BB/2, 512, smem>>>(W_hh, b_ih, b_hh, out);
    }
}

// round 17
// speedup vs baseline: 2.1366x; 1.0551x over previous
#include <cuda_runtime.h>
#include <cuda_fp16.h>
#include <math.h>
#include <stdint.h>

// Problem dims
#define BB 256
#define DD 128
#define FF 8
#define TT 128
#define HH 128
#define KDIM (DD*FF)        // 1024
#define G4H (4*HH)          // 512

// Scratch (device globals; no allocation allowed)
__device__ float g_ex[BB*DD];
__device__ float g_a[BB*DD];
__device__ __align__(256) float g_y[BB*TT*G4H];               // y[b][t][g], 64 MB
__device__ __align__(256) __half g_xh[(size_t)BB*TT*KDIM];    // [b][t][k] fp16, 64 MB
__device__ __align__(256) __half g_wh[G4H*KDIM];              // [g][k] fp16

// ---------------- baseline-PTX helpers ----------------
__device__ __forceinline__ uint32_t smem_u32(const void* p) {
    uint32_t a;
    asm("{ .reg .u64 t; cvta.to.shared.u64 t, %1; cvt.u32.u64 %0, t; }" : "=r"(a) : "l"(p));
    return a;
}
#define SWZ128(o) ((o) ^ (((o) >> 3) & 0x70))

#define CP_ASYNC16(dst, src) \
    asm volatile("cp.async.cg.shared.global [%0], [%1], 16;" :: "r"(dst), "l"(src))
#define CP_COMMIT() asm volatile("cp.async.commit_group;" ::: "memory")
#define CP_WAIT(n)  asm volatile("cp.async.wait_group %0;" :: "n"(n) : "memory")

#define LDSM_X4(r0, r1, r2, r3, a) \
    asm volatile("ldmatrix.sync.aligned.m8n8.x4.shared.b16 {%0,%1,%2,%3}, [%4];" \
        : "=r"(r0), "=r"(r1), "=r"(r2), "=r"(r3) : "r"(a))

#define MMA16816F16(d, a0, a1, a2, a3, b0, b1) \
    asm volatile("mma.sync.aligned.m16n8k16.row.col.f32.f16.f16.f32 " \
        "{%0,%1,%2,%3},{%4,%5,%6,%7},{%8,%9},{%0,%1,%2,%3};" \
        : "+f"((d)[0]), "+f"((d)[1]), "+f"((d)[2]), "+f"((d)[3]) \
        : "r"(a0), "r"(a1), "r"(a2), "r"(a3), "r"(b0), "r"(b1))

#define FMA_F32X2(d, a, b) \
    asm("fma.rn.f32x2 %0, %1, %2, %0;" : "+l"(d) : "l"(a), "l"(b))
__device__ __forceinline__ float p2lo(unsigned long long v) {
    return __uint_as_float((unsigned)(v & 0xffffffffull));
}
__device__ __forceinline__ float p2hi(unsigned long long v) {
    return __uint_as_float((unsigned)(v >> 32));
}

// ---------------------------------------------------------------------------
// K1: ex[b,d] = sum_{f,t} input[b,d,f,t] * w_x[f*T+t]; one warp per (b,d)
// ---------------------------------------------------------------------------
__global__ void k1_ex(const float* __restrict__ input, const float* __restrict__ w_attn) {
    const float* w_x = w_attn + 2*HH;
    int warp = (blockIdx.x * blockDim.x + threadIdx.x) >> 5;
    int lane = threadIdx.x & 31;
    if (warp >= BB*DD) return;
    const float4* base = (const float4*)(input + (size_t)warp * KDIM);
    const float4* w4 = (const float4*)w_x;
    float s = 0.f;
    #pragma unroll
    for (int i = 0; i < 8; i++) {
        float4 v = base[lane + 32*i];
        float4 w = __ldg(&w4[lane + 32*i]);
        s += v.x*w.x + v.y*w.y + v.z*w.z + v.w*w.w;
    }
    #pragma unroll
    for (int o = 16; o > 0; o >>= 1) s += __shfl_down_sync(0xffffffffu, s, o);
    if (lane == 0) g_ex[warp] = s;
}

// ---------------------------------------------------------------------------
// K1b: a[b,:] = softmax(ex[b,:]) over D=128
// ---------------------------------------------------------------------------
__global__ void k1b_softmax() {
    __shared__ float red[4];
    int b = blockIdx.x;
    int d = threadIdx.x;
    int lane = d & 31, w = d >> 5;
    float v = g_ex[b*DD + d];
    float m = v;
    #pragma unroll
    for (int o = 16; o > 0; o >>= 1) m = fmaxf(m, __shfl_xor_sync(0xffffffffu, m, o));
    if (lane == 0) red[w] = m;
    __syncthreads();
    m = fmaxf(fmaxf(red[0], red[1]), fmaxf(red[2], red[3]));
    float e = expf(v - m);
    float s = e;
    #pragma unroll
    for (int o = 16; o > 0; o >>= 1) s += __shfl_xor_sync(0xffffffffu, s, o);
    __syncthreads();
    if (lane == 0) red[w] = s;
    __syncthreads();
    s = red[0] + red[1] + red[2] + red[3];
    g_a[b*DD + d] = e / s;
}

// ---------------------------------------------------------------------------
// kW: round W_ih to fp16, [g][k] K-major
// ---------------------------------------------------------------------------
__global__ void k_wsplit(const float* __restrict__ W_ih) {
    int idx = blockIdx.x * 256 + threadIdx.x;
    if (idx >= G4H*KDIM/2) return;
    float2 v = ((const float2*)W_ih)[idx];
    __half h0 = __float2half_rn(v.x), h1 = __float2half_rn(v.y);
    ((uint32_t*)g_wh)[idx] = (uint32_t)__half_as_ushort(h0) | ((uint32_t)__half_as_ushort(h1) << 16);
}

// ---------------------------------------------------------------------------
// k_prep: xhat = a[b,k>>3] * input[b,k,t]; fp16 round; transpose to [b][t][k]
// (clock canary: identical since round 10 — compare dur across runs)
// ---------------------------------------------------------------------------
__global__ __launch_bounds__(256) void k_prep(const float* __restrict__ input) {
    __shared__ float tile[64][129];
    int b = blockIdx.y, k0 = blockIdx.x * 64;
    int tid = threadIdx.x;
    int lane = tid & 31, r = tid >> 5;
    #pragma unroll
    for (int it = 0; it < 8; it++) {
        int row = it*8 + r;
        const float4 v = *(const float4*)(input + ((size_t)b*KDIM + k0 + row)*TT + lane*4);
        float s = g_a[b*DD + ((k0 + row) >> 3)];
        tile[row][lane*4+0] = v.x*s;
        tile[row][lane*4+1] = v.y*s;
        tile[row][lane*4+2] = v.z*s;
        tile[row][lane*4+3] = v.w*s;
    }
    __syncthreads();
    int kk = lane * 2;
    #pragma unroll
    for (int it = 0; it < 16; it++) {
        int t = it*8 + r;
        __half h0 = __float2half_rn(tile[kk][t]);
        __half h1 = __float2half_rn(tile[kk+1][t]);
        uint32_t hp = (uint32_t)__half_as_ushort(h0) | ((uint32_t)__half_as_ushort(h1) << 16);
        size_t base = (size_t)(b*TT + t)*(KDIM/2) + (k0 >> 1);
        ((uint32_t*)g_xh)[base + lane] = hp;
    }
}

// ---------------------------------------------------------------------------
// k2_mma: single-pass fp16 (xh * wh), CHUNK_K=64 (128B rows, SW128),
// 2-stage cp.async double buffer, 2 CTAs/SM. Halved barrier/wait count.
// ---------------------------------------------------------------------------
#define S_A 0
#define S_B 16384
#define K2_STAGE 32768
#define K2_SMEM (2*K2_STAGE)

__device__ __forceinline__ void k2_load_chunk(uint32_t dstbase, int b, int gbase,
                                              int k0, int tid) {
    const char* pxh = (const char*)g_xh;
    const char* pwh = (const char*)g_wh;
    #pragma unroll
    for (int q = 0; q < 4; q++) {
        int u = tid + 256*q;          // 0..1023
        int row = u >> 3, l8 = u & 7; // 128 rows x 8 16B-units (128B/row)
        uint32_t sw = SWZ128((uint32_t)(row*128 + l8*16));
        size_t aoff = ((size_t)(b*TT + row)*KDIM + k0)*2 + l8*16;
        size_t boff = ((size_t)(gbase + row)*KDIM + k0)*2 + l8*16;
        CP_ASYNC16(dstbase + S_A + sw, pxh + aoff);
        CP_ASYNC16(dstbase + S_B + sw, pwh + boff);
    }
}

__global__ __launch_bounds__(256, 2) void k2_mma() {
    extern __shared__ char smem[];
    uint32_t sb = smem_u32(smem);
    int tid = threadIdx.x;
    int lane = tid & 31, wid = tid >> 5;
    int b = blockIdx.y, gbase = blockIdx.x * 128;
    int wt = wid & 3;        // t block: wt*32
    int wg = wid >> 2;       // g block: wg*64

    float acc[2][8][4];
    #pragma unroll
    for (int mi = 0; mi < 2; mi++)
        #pragma unroll
        for (int ni = 0; ni < 8; ni++)
            #pragma unroll
            for (int q = 0; q < 4; q++) acc[mi][ni][q] = 0.f;

    int a_row_base = wt*32 + (lane & 15);
    int a_col = (lane >> 4) * 16;
    int b_row_base = wg*64 + ((lane >> 4) * 8) + (lane & 7);
    int b_col = ((lane >> 3) & 1) * 16;

    k2_load_chunk(sb, b, gbase, 0, tid);
    CP_COMMIT();

    int buf = 0;
    for (int chunk = 0; chunk < 16; chunk++) {
        if (chunk < 15) {
            k2_load_chunk(sb + (buf ^ 1)*K2_STAGE, b, gbase, (chunk+1)*64, tid);
            CP_COMMIT();
            CP_WAIT(1);
        } else {
            CP_WAIT(0);
        }
        __syncthreads();

        uint32_t base = sb + buf*K2_STAGE;
        #pragma unroll
        for (int ks = 0; ks < 4; ks++) {
            uint32_t ah[2][4];
            #pragma unroll
            for (int mi = 0; mi < 2; mi++) {
                uint32_t off = SWZ128((uint32_t)((a_row_base + mi*16)*128 + ks*32 + a_col));
                LDSM_X4(ah[mi][0], ah[mi][1], ah[mi][2], ah[mi][3], base + S_A + off);
            }
            #pragma unroll
            for (int p = 0; p < 4; p++) {
                uint32_t off = SWZ128((uint32_t)((b_row_base + p*16)*128 + ks*32 + b_col));
                uint32_t bh[4];
                LDSM_X4(bh[0], bh[1], bh[2], bh[3], base + S_B + off);
                #pragma unroll
                for (int mi = 0; mi < 2; mi++)
                    #pragma unroll
                    for (int j = 0; j < 2; j++)
                        MMA16816F16(acc[mi][p*2+j], ah[mi][0], ah[mi][1], ah[mi][2], ah[mi][3],
                                    bh[j*2], bh[j*2+1]);
            }
        }
        __syncthreads();
        buf ^= 1;
    }

    // Epilogue
    int r0 = wt*32 + (lane >> 2);
    int c0 = gbase + wg*64 + (lane & 3)*2;
    #pragma unroll
    for (int mi = 0; mi < 2; mi++) {
        #pragma unroll
        for (int ni = 0; ni < 8; ni++) {
            int row = r0 + mi*16;
            int col = c0 + ni*8;
            float* p0 = g_y + (size_t)(b*TT + row)*G4H + col;
            float* p1 = g_y + (size_t)(b*TT + row + 8)*G4H + col;
            *(float2*)p0 = make_float2(acc[mi][ni][0], acc[mi][ni][1]);
            *(float2*)p1 = make_float2(acc[mi][ni][2], acc[mi][ni][3]);
        }
    }
}

// ---------------------------------------------------------------------------
// K3: persistent recurrence (round-12 proven version: two barriers, gs array,
// WREG=64 regs + smem pitch-68). Reverted — single-barrier variant was slower.
// ---------------------------------------------------------------------------
#define WREG 64
#define WP_PITCH 68

__device__ __forceinline__ float sigm(float x) { return 1.f / (1.f + expf(-x)); }

__global__ __launch_bounds__(512, 1) void k3_lstm(const float* __restrict__ W_hh,
                                                  const float* __restrict__ b_ih,
                                                  const float* __restrict__ b_hh,
                                                  float* __restrict__ out) {
    extern __shared__ float sm[];
    float* Wp   = sm;
    float* hs   = Wp + G4H*WP_PITCH;
    float* cs   = hs + 2*HH;
    float* gs   = cs + 2*HH;
    float* bias = gs + 2*G4H;

    int tid = threadIdx.x;
    int b0 = blockIdx.x * 2;
    const int g = tid;

    for (int idx = tid; idx < G4H*(HH-WREG); idx += 512) {
        int gg = idx >> 6;
        int kk = idx & 63;
        Wp[gg*WP_PITCH + kk] = W_hh[(size_t)gg*HH + WREG + kk];
    }
    bias[tid] = b_ih[tid] + b_hh[tid];
    if (tid < 2*HH) { hs[tid] = 0.f; cs[tid] = 0.f; }

    ulonglong2 wr2[16];
    #pragma unroll
    for (int i = 0; i < 16; i++)
        wr2[i] = *(const ulonglong2*)(W_hh + (size_t)g*HH + 4*i);

    __syncthreads();

    const float myBias = bias[g];
    const float* wprow = Wp + g*WP_PITCH;
    const float* h0 = hs;
    const float* h1 = hs + HH;
    const float* y0p = g_y + ((size_t)b0*TT)*G4H + g;
    const float* y1p = g_y + ((size_t)(b0+1)*TT)*G4H + g;

    float yn0 = *y0p, yn1 = *y1p;

    for (int t = 0; t < TT; t++) {
        float base0 = yn0 + myBias;
        float base1 = yn1 + myBias;
        if (t + 1 < TT) {
            yn0 = y0p[(size_t)(t+1)*G4H];
            yn1 = y1p[(size_t)(t+1)*G4H];
        }
        unsigned long long a0p = 0ull, a0q = 0ull, a1p = 0ull, a1q = 0ull;
        #pragma unroll
        for (int i = 0; i < 16; i++) {
            ulonglong2 w = wr2[i];
            ulonglong2 a = *(const ulonglong2*)(h0 + 4*i);
            ulonglong2 bv = *(const ulonglong2*)(h1 + 4*i);
            FMA_F32X2(a0p, w.x, a.x);
            FMA_F32X2(a0q, w.y, a.y);
            FMA_F32X2(a1p, w.x, bv.x);
            FMA_F32X2(a1q, w.y, bv.y);
        }
        #pragma unroll
        for (int i = 0; i < 16; i++) {
            ulonglong2 w = *(const ulonglong2*)(wprow + 4*i);
            ulonglong2 a = *(const ulonglong2*)(h0 + WREG + 4*i);
            ulonglong2 bv = *(const ulonglong2*)(h1 + WREG + 4*i);
            FMA_F32X2(a0p, w.x, a.x);
            FMA_F32X2(a0q, w.y, a.y);
            FMA_F32X2(a1p, w.x, bv.x);
            FMA_F32X2(a1q, w.y, bv.y);
        }
        gs[g]       = base0 + p2lo(a0p) + p2hi(a0p) + p2lo(a0q) + p2hi(a0q);
        gs[G4H + g] = base1 + p2lo(a1p) + p2hi(a1p) + p2lo(a1q) + p2hi(a1q);
        __syncthreads();
        if (tid < 2*HH) {
            int bb = tid >> 7;
            int j  = tid & (HH-1);
            const float* G = gs + bb*G4H;
            float iv = G[j], fv = G[HH + j], gv = G[2*HH + j], ov = G[3*HH + j];
            float c  = cs[bb*HH + j];
            float cn = sigm(fv)*c + sigm(iv)*tanhf(gv);
            float hn = sigm(ov)*tanhf(cn);
            cs[bb*HH + j] = cn;
            hs[bb*HH + j] = hn;
            out[((size_t)(b0+bb)*TT + t)*HH + j] = hn;
        }
        __syncthreads();
    }
}

// ---------------------------------------------------------------------------
extern "C" void kernel_launch(void* const* d_in, const int* in_sizes, int n_in,
                              void* d_out, int out_size) {
    const float* input  = (const float*)d_in[0];  // (B,D,F,T)
    const float* w_attn = (const float*)d_in[1];  // (F*T + 2H,)
    // d_in[2] = b_attn (unused: softmax is shift-invariant)
    const float* W_ih   = (const float*)d_in[3];  // (4H, D*F)
    const float* W_hh   = (const float*)d_in[4];  // (4H, H)
    const float* b_ih   = (const float*)d_in[5];  // (4H,)
    const float* b_hh   = (const float*)d_in[6];  // (4H,)
    float* out = (float*)d_out;                   // (B, T, H)

    k1_ex<<<4096, 256>>>(input, w_attn);
    k1b_softmax<<<BB, DD>>>();
    k_wsplit<<<(G4H*KDIM/2 + 255)/256, 256>>>(W_ih);
    {
        dim3 grid(KDIM/64, BB);
        k_prep<<<grid, 256>>>(input);
    }
    {
        cudaFuncSetAttribute(k2_mma, cudaFuncAttributeMaxDynamicSharedMemorySize, K2_SMEM);
        dim3 grid(G4H/128, BB);
        k2_mma<<<grid, 256, K2_SMEM>>>();
    }
    {
        int smem = (G4H*WP_PITCH + 2*HH + 2*HH + 2*G4H + G4H) * (int)sizeof(float);
        cudaFuncSetAttribute(k3_lstm, cudaFuncAttributeMaxDynamicSharedMemorySize, smem);
        k3_lstm<<<BB/2, 512, smem>>>(W_hh, b_ih, b_hh, out);
    }
}